// round 4
// baseline (speedup 1.0000x reference)
#include <cuda_runtime.h>
#include <math.h>

#define N_ATOMS 4096
#define NRBF    16
#define NHID    64
#define NSLICE  16
#define SLICE   (N_ATOMS / NSLICE)   // 256 j per slice
#define IPB     128                  // atoms i per block == threads per block
#define NBI     (N_ATOMS / IPB)      // 32 i-tiles

// ---- scratch (no allocations allowed) ----
__device__ float g_feats_part[NSLICE * N_ATOMS * NRBF]; // 4 MB partial features
__device__ float g_atomic_e[N_ATOMS];                   // per-atom energies

// 1/(2*eta^2), eta = 0.5*(5.0-0.5)/16 = 9/64 -> A = 2048/81
#define RBF_A 25.28395061728395f
#define PI_OVER_CUT 0.6283185307179586f  // pi / 5.0

// ============================================================
// Kernel 1: pairwise RBF features (partial, per j-slice)
// ============================================================
__global__ __launch_bounds__(IPB)
void feats_kernel(const float* __restrict__ pos,
                  const float* __restrict__ centers)
{
    __shared__ float4 sp[SLICE];

    const int i  = blockIdx.x * IPB + threadIdx.x;  // my atom
    const int s  = blockIdx.y;                      // j-slice
    const int j0 = s * SLICE;

    // stage the j-slice positions into shared (float4 for single LDS.128 broadcast)
    for (int t = threadIdx.x; t < SLICE; t += IPB) {
        int j = j0 + t;
        sp[t] = make_float4(pos[3 * j], pos[3 * j + 1], pos[3 * j + 2], 0.0f);
    }

    // my position + RBF centers into registers
    const float xi = pos[3 * i];
    const float yi = pos[3 * i + 1];
    const float zi = pos[3 * i + 2];

    float c[NRBF];
    #pragma unroll
    for (int k = 0; k < NRBF; k++) c[k] = centers[k];

    __syncthreads();

    float f[NRBF];
    #pragma unroll
    for (int k = 0; k < NRBF; k++) f[k] = 0.0f;

    #pragma unroll 4
    for (int t = 0; t < SLICE; t++) {
        float4 p  = sp[t];                  // broadcast across the warp
        float dx = xi - p.x;
        float dy = yi - p.y;
        float dz = zi - p.z;
        float sq = fmaf(dx, dx, fmaf(dy, dy, dz * dz));
        if (sq > 0.0f && sq < 25.0f) {      // excludes self (sq==0) and far pairs
            float d = sqrtf(sq);
            float w = 0.5f + 0.5f * __cosf(d * PI_OVER_CUT);
            #pragma unroll
            for (int k = 0; k < NRBF; k++) {
                float tt = d - c[k];
                float g  = __expf(-RBF_A * tt * tt);
                f[k] = fmaf(w, g, f[k]);
            }
        }
    }

    // write 16 partial features (64B aligned -> 4x STG.128)
    float4* out = reinterpret_cast<float4*>(
        &g_feats_part[((size_t)s * N_ATOMS + i) * NRBF]);
    out[0] = make_float4(f[0],  f[1],  f[2],  f[3]);
    out[1] = make_float4(f[4],  f[5],  f[6],  f[7]);
    out[2] = make_float4(f[8],  f[9],  f[10], f[11]);
    out[3] = make_float4(f[12], f[13], f[14], f[15]);
}

// ============================================================
// Kernel 2: per-atom MLP (16 -> 64 -> 64 -> 1, SiLU)
// one block per atom, 64 threads = hidden units
// ============================================================
__device__ __forceinline__ float silu_f(float a)
{
    return a / (1.0f + __expf(-a));
}

__global__ __launch_bounds__(NHID)
void mlp_kernel(const float* __restrict__ W1, const float* __restrict__ b1,
                const float* __restrict__ W2, const float* __restrict__ b2,
                const float* __restrict__ W3, const float* __restrict__ b3)
{
    __shared__ float sf[NRBF];
    __shared__ float sh1[NHID];
    __shared__ float red[2];

    const int i = blockIdx.x;
    const int t = threadIdx.x;   // 0..63

    // reduce slice partials -> features
    if (t < NRBF) {
        float acc = 0.0f;
        #pragma unroll
        for (int s = 0; s < NSLICE; s++)
            acc += g_feats_part[((size_t)s * N_ATOMS + i) * NRBF + t];
        sf[t] = acc;
    }
    __syncthreads();

    // layer 1: 16 -> 64
    float a = b1[t];
    #pragma unroll
    for (int k = 0; k < NRBF; k++)
        a = fmaf(sf[k], W1[k * NHID + t], a);
    sh1[t] = silu_f(a);
    __syncthreads();

    // layer 2: 64 -> 64
    float a2 = b2[t];
    #pragma unroll
    for (int u = 0; u < NHID; u++)
        a2 = fmaf(sh1[u], W2[u * NHID + t], a2);
    float v = silu_f(a2) * W3[t];   // layer 3 partial product

    // reduce 64 -> 1
    #pragma unroll
    for (int o = 16; o > 0; o >>= 1)
        v += __shfl_down_sync(0xffffffff, v, o);
    if ((t & 31) == 0) red[t >> 5] = v;
    __syncthreads();
    if (t == 0)
        g_atomic_e[i] = red[0] + red[1] + b3[0];
}

// ============================================================
// Kernel 3: deterministic sum of per-atom energies
// ============================================================
__global__ __launch_bounds__(1024)
void reduce_kernel(float* __restrict__ out)
{
    __shared__ float sh[1024];
    const int t = threadIdx.x;
    float v = 0.0f;
    #pragma unroll
    for (int i = t; i < N_ATOMS; i += 1024)
        v += g_atomic_e[i];
    sh[t] = v;
    __syncthreads();
    #pragma unroll
    for (int s = 512; s > 0; s >>= 1) {
        if (t < s) sh[t] += sh[t + s];
        __syncthreads();
    }
    if (t == 0) out[0] = sh[0];
}

// ============================================================
extern "C" void kernel_launch(void* const* d_in, const int* in_sizes, int n_in,
                              void* d_out, int out_size)
{
    const float* pos     = (const float*)d_in[0];
    const float* centers = (const float*)d_in[1];
    const float* W1      = (const float*)d_in[2];
    const float* b1      = (const float*)d_in[3];
    const float* W2      = (const float*)d_in[4];
    const float* b2      = (const float*)d_in[5];
    const float* W3      = (const float*)d_in[6];
    const float* b3      = (const float*)d_in[7];

    dim3 grid_f(NBI, NSLICE);
    feats_kernel<<<grid_f, IPB>>>(pos, centers);
    mlp_kernel<<<N_ATOMS, NHID>>>(W1, b1, W2, b2, W3, b3);
    reduce_kernel<<<1, 1024>>>((float*)d_out);
}